// round 3
// baseline (speedup 1.0000x reference)
#include <cuda_runtime.h>
#include <cstdint>

// Problem constants
#define Bn 16
#define Cn 256
#define Hn 128
#define Wn 128
#define HW (Hn*Wn)            // 16384 = 2^14
#define CHW (Cn*HW)           // 4194304 = 2^22
#define CHW4 (CHW/4)          // 1048576 = 2^20
#define HW4 (HW/4)            // 4096

// Chunking: 4 batches per chunk -> 64 MiB of x, fits in ~126 MB L2
#define BCHUNK 4
#define NCHUNK (Bn/BCHUNK)    // 4
#define CGROUPS 8             // split-C groups in reduce
#define CPER (Cn/CGROUPS)     // 32 channels per group
#define CHUNK_PIX (BCHUNK*HW)    // 65536 outputs per chunk
#define CHUNK_PIX4 (CHUNK_PIX/4) // 16384

// Scratch (__device__ globals; reused serially across chunks)
__device__ float g_part[CGROUPS * CHUNK_PIX]; // 2 MiB partial channel sums
__device__ float g_x1[CHUNK_PIX];             // 256 KiB conv result

// ---------------------------------------------------------------------------
// K1: partial channel sums for one chunk.
// 131072 threads; thread i: group g = i>>14, j = i&16383 (float4 pixel id).
// part4[i] = sum over 32 channels of x[b, g*32+c, hw4]
// ---------------------------------------------------------------------------
__global__ void __launch_bounds__(256) reduce_part_kernel(const float4* __restrict__ x,
                                                          float4* __restrict__ part4) {
    int i = blockIdx.x * blockDim.x + threadIdx.x;  // 0 .. 131071
    int g = i >> 14;            // 0..7
    int j = i & 16383;          // chunk pixel (float4)
    int bl  = j >> 12;          // 0..3 batch-in-chunk
    int hw4 = j & 4095;

    const float4* p = x + (size_t)bl * CHW4 + (size_t)g * CPER * HW4 + hw4;

    float4 acc = make_float4(0.f, 0.f, 0.f, 0.f);
#pragma unroll 8
    for (int c = 0; c < CPER; ++c) {
        float4 v = p[(size_t)c * HW4];
        acc.x += v.x; acc.y += v.y; acc.z += v.z; acc.w += v.w;
    }
    part4[i] = acc;
}

// ---------------------------------------------------------------------------
// K2: combine partials + 3x3 conv (cross-correlation, zero pad) in one pass.
// 65536 threads, one per chunk pixel. All loads hit L2 (2.25 MiB footprint).
// ---------------------------------------------------------------------------
__global__ void __launch_bounds__(256) conv_combine_kernel(const float* __restrict__ part,
                                                           const float* __restrict__ f,
                                                           float* __restrict__ x1) {
    int i = blockIdx.x * blockDim.x + threadIdx.x;  // 0 .. 65535
    int bl = i >> 14;
    int hw = i & (HW - 1);
    int h  = hw >> 7;
    int w  = hw & (Wn - 1);

    float fw[9];
#pragma unroll
    for (int k = 0; k < 9; ++k) fw[k] = f[k];

    int base = bl * HW;
    float acc = 0.f;
#pragma unroll
    for (int di = 0; di < 3; ++di) {
        int hh = h + di - 1;
        if (hh < 0 || hh >= Hn) continue;
#pragma unroll
        for (int dj = 0; dj < 3; ++dj) {
            int ww = w + dj - 1;
            if (ww < 0 || ww >= Wn) continue;
            int pos = base + hh * Wn + ww;
            float sv = 0.f;
#pragma unroll
            for (int g = 0; g < CGROUPS; ++g)
                sv += part[g * CHUNK_PIX + pos];
            acc += sv * fw[di * 3 + dj];
        }
    }
    x1[i] = acc;
}

// ---------------------------------------------------------------------------
// K3: out = x - x1 (broadcast over C) for one chunk.
// x reads should hit L2 (loaded by K1); out stored evict-first (__stcs).
// 4194304 float4 elements.
// ---------------------------------------------------------------------------
__global__ void __launch_bounds__(256) sub_kernel(const float4* __restrict__ x,
                                                  const float4* __restrict__ x1,
                                                  float4* __restrict__ out) {
    int i = blockIdx.x * blockDim.x + threadIdx.x;  // 0 .. 4194303
    int bl  = i >> 20;          // batch-in-chunk (CHW4 = 2^20)
    int hw4 = i & 4095;
    float4 xv = x[i];
    float4 bv = __ldg(&x1[(bl << 12) + hw4]);
    float4 o;
    o.x = xv.x - bv.x;
    o.y = xv.y - bv.y;
    o.z = xv.z - bv.z;
    o.w = xv.w - bv.w;
    __stcs(&out[i], o);
}

// ---------------------------------------------------------------------------
extern "C" void kernel_launch(void* const* d_in, const int* in_sizes, int n_in,
                              void* d_out, int out_size) {
    const float* x = (const float*)d_in[0];   // (16,256,128,128) fp32
    const float* f = (const float*)d_in[1];   // (3,3) fp32
    float* out = (float*)d_out;

    static float* part_ptr = nullptr;
    static float* x1_ptr   = nullptr;
    if (part_ptr == nullptr) {
        cudaGetSymbolAddress((void**)&part_ptr, g_part);
        cudaGetSymbolAddress((void**)&x1_ptr,   g_x1);
    }

    for (int c = 0; c < NCHUNK; ++c) {
        const float4* xc  = (const float4*)x   + (size_t)c * BCHUNK * CHW4;
        float4*       oc  = (float4*)out       + (size_t)c * BCHUNK * CHW4;

        // K1: partial channel sums (reads 64 MiB DRAM, warms L2 with x chunk)
        reduce_part_kernel<<<(CGROUPS * CHUNK_PIX4) / 256, 256>>>(
            xc, (float4*)part_ptr);

        // K2: combine + conv (tiny, L2-resident)
        conv_combine_kernel<<<CHUNK_PIX / 256, 256>>>(part_ptr, f, x1_ptr);

        // K3: broadcast subtract (x reads from L2, out writes to DRAM)
        sub_kernel<<<(BCHUNK * CHW4) / 256, 256>>>(
            xc, (const float4*)x1_ptr, oc);
    }
}